// round 7
// baseline (speedup 1.0000x reference)
#include <cuda_runtime.h>
#include <math.h>

#define NB    300
#define BATCH 8
#define RSEL  36
#define NW    10
#define CCH   256
#define GRID  14
#define SPAN  64
#define NSEL  (BATCH * RSEL)
#define NCGB  4              // channel-group blocks (64 channels each)
#define CONF_THR 0.3f
#define IOU_THR  0.7f

// Inter-kernel scratch (device globals; no allocations allowed)
__device__ float g_cx[NSEL * SPAN];
__device__ float g_cy[NSEL * SPAN];
__device__ int   g_meta[NSEL * 8];   // xlo, Lx, ylo, Ly, valid, lv, 0, 0

// ---------------------------------------------------------------------------
// K1: fused NMS: threshold + stable sort + symmetric masks + Jacobi fixpoint
// suppression + stable selection + level + separable coefficients.
// One block per batch, 320 threads.
// ---------------------------------------------------------------------------
__global__ void nms_kernel(const float* __restrict__ boxes,
                           const float* __restrict__ scores)
{
    const int b = blockIdx.x;
    const int t = threadIdx.x;

    __shared__ float    s_raw[NB];
    __shared__ int      s_order[NB];
    __shared__ float4   s_box[NB];
    __shared__ float    s_area[NB];
    __shared__ float    s_ss[NB];
    __shared__ unsigned s_pre[NB][NW];      // predecessor masks (bits i<j)
    __shared__ unsigned s_keep[NW];
    __shared__ unsigned s_v[NW];
    __shared__ int      s_sel[RSEL];
    __shared__ float4   s_selbox[RSEL];
    __shared__ float    s_coef[RSEL][2][SPAN];

    // threshold
    for (int i = t; i < NB; i += blockDim.x) {
        float sc = scores[b * NB + i];
        s_raw[i] = (sc > CONF_THR) ? sc : -INFINITY;
    }
    for (int e = t; e < RSEL * 2 * SPAN; e += blockDim.x)
        ((float*)s_coef)[e] = 0.0f;
    __syncthreads();

    // stable descending rank sort
    for (int i = t; i < NB; i += blockDim.x) {
        float si = s_raw[i];
        int rank = 0;
        for (int j = 0; j < NB; j++) {
            float sj = s_raw[j];
            if (sj > si || (sj == si && j < i)) rank++;
        }
        s_order[rank] = i;
    }
    __syncthreads();

    // gather sorted boxes / areas / scores
    for (int r = t; r < NB; r += blockDim.x) {
        int i = s_order[r];
        float4 bb = ((const float4*)boxes)[(size_t)b * NB + i];
        s_box[r]  = bb;
        s_area[r] = (bb.z - bb.x) * (bb.w - bb.y);
        s_ss[r]   = s_raw[i];
    }
    __syncthreads();

    // validity words via ballot (thread t owns bit t)
    {
        int pred = (t < NB) && (s_ss[t] > -INFINITY);
        unsigned word = __ballot_sync(0xffffffffu, pred);
        if ((t & 31) == 0) { s_v[t >> 5] = word; s_keep[t >> 5] = word; }
    }

    // predecessor masks: row j gets bits for i < j with iou > thr
    if (t < NB) {
        const int j = t;
        float4 a = s_box[j];
        float area_a = s_area[j];
        int wmax = (j + 31) >> 5;             // words containing some i<j
        for (int w = 0; w < NW; w++) {
            unsigned bits = 0;
            if (w < wmax) {
                int kend = min(32, j - w * 32);
                for (int k = 0; k < kend; k++) {
                    float4 bb = s_box[w * 32 + k];
                    float ltx = fmaxf(a.x, bb.x);
                    float lty = fmaxf(a.y, bb.y);
                    float rbx = fminf(a.z, bb.z);
                    float rby = fminf(a.w, bb.w);
                    float iw = fmaxf(rbx - ltx, 0.0f);
                    float ih = fmaxf(rby - lty, 0.0f);
                    float inter = iw * ih;
                    float iou = inter / (area_a + s_area[w * 32 + k] - inter + 1e-9f);
                    if (iou > IOU_THR) bits |= (1u << k);
                }
            }
            s_pre[j][w] = bits;
        }
    }
    __syncthreads();

    // Jacobi fixpoint of keep[j] = v[j] & !OR_{i<j}(keep[i] & edge(i,j)).
    // Unique fixpoint == sequential greedy NMS; converges in DAG-depth iters.
    int changed = 1;
    while (changed) {
        unsigned supany = 0;
        if (t < NB) {
            #pragma unroll
            for (int w = 0; w < NW; w++) supany |= s_keep[w] & s_pre[t][w];
        }
        int vbit = (t < NB) ? ((s_v[t >> 5] >> (t & 31)) & 1) : 0;
        int oldb = (t < NB) ? ((s_keep[t >> 5] >> (t & 31)) & 1) : 0;
        int newb = vbit && !supany;
        int ch = (newb != oldb);
        __syncthreads();                       // reads of s_keep done
        unsigned word = __ballot_sync(0xffffffffu, newb);
        if ((t & 31) == 0) s_keep[t >> 5] = word;
        changed = __syncthreads_or(ch);
    }

    // stable partition: kept first, then suppressed (bit scan)
    if (t == 0) {
        int cnt = 0;
        for (int w = 0; w < NW && cnt < RSEL; w++) {
            unsigned bits = s_keep[w];
            while (bits && cnt < RSEL) {
                int k = __ffs(bits) - 1; bits &= bits - 1;
                s_sel[cnt++] = w * 32 + k;
            }
        }
        for (int w = 0; w < NW && cnt < RSEL; w++) {
            unsigned bits = ~s_keep[w];
            if (w == NW - 1) bits &= (1u << (NB - (NW - 1) * 32)) - 1;
            while (bits && cnt < RSEL) {
                int k = __ffs(bits) - 1; bits &= bits - 1;
                s_sel[cnt++] = w * 32 + k;
            }
        }
    }
    __syncthreads();

    // selected boxes, validity, level -> packed meta
    if (t < RSEL) {
        int j = s_sel[t];
        float4 bb = s_box[j];
        s_selbox[t] = bb;
        int valid = (s_keep[j >> 5] >> (j & 31)) & 1u;
        float dx = bb.z - bb.x, dy = bb.w - bb.y;
        float sz = sqrtf(fmaxf(dx * dx + dy * dy, 1e-12f));
        float lvf = fminf(fmaxf(floorf(4.0f + log2f(sz / 224.0f * 4.0f)), 2.0f), 5.0f);
        int base = (b * RSEL + t) * 8;
        g_meta[base + 4] = valid;
        g_meta[base + 5] = (int)lvf - 2;
        g_meta[base + 6] = 0;
        g_meta[base + 7] = 0;
    }
    __syncthreads();

    // separable coefficient build: task t -> (box r = t>>1, axis = t&1)
    if (t < 2 * RSEL) {
        const int r = t >> 1, axis = t & 1;
        float4 bb = s_selbox[r];
        float dx = bb.z - bb.x, dy = bb.w - bb.y;
        float sz = sqrtf(fmaxf(dx * dx + dy * dy, 1e-12f));
        float lvf = fminf(fmaxf(floorf(4.0f + log2f(sz / 224.0f * 4.0f)), 2.0f), 5.0f);
        int lv = (int)lvf - 2;
        int H = 200 >> lv;
        float c1 = axis ? bb.y : bb.x;
        float c2 = axis ? bb.w : bb.z;
        float rs = fmaxf(c2 - c1, 1.0f);

        int lo = 1 << 30, hi = -(1 << 30);
        #pragma unroll
        for (int s = 0; s < GRID; s++) {
            float g = ((float)s + 0.5f) / (float)GRID;
            float P = c1 + rs * g;
            if (P < -1.0f || P > (float)H) continue;
            float p = fminf(fmaxf(P, 0.0f), (float)(H - 1));
            int p0 = (int)floorf(p);
            int p1 = min(p0 + 1, H - 1);
            lo = min(lo, p0); hi = max(hi, p1);
        }
        int L;
        if (lo > hi) { lo = 0; L = 0; }
        else {
            L = hi - lo + 1;
            #pragma unroll
            for (int s = 0; s < GRID; s++) {
                float g = ((float)s + 0.5f) / (float)GRID;
                float P = c1 + rs * g;
                if (P < -1.0f || P > (float)H) continue;
                float p = fminf(fmaxf(P, 0.0f), (float)(H - 1));
                int p0 = (int)floorf(p);
                int p1 = min(p0 + 1, H - 1);
                float lp = p - (float)p0;
                s_coef[r][axis][p0 - lo] += 1.0f - lp;
                s_coef[r][axis][p1 - lo] += lp;
            }
        }
        int base = (b * RSEL + r) * 8 + axis * 2;
        g_meta[base + 0] = lo;
        g_meta[base + 1] = L;
    }
    __syncthreads();

    // coalesced coefficient writeback
    for (int e = t; e < RSEL * 2 * SPAN; e += blockDim.x) {
        int r    = e / (2 * SPAN);
        int axis = (e >> 6) & 1;
        int k    = e & (SPAN - 1);
        float v  = s_coef[r][axis][k];
        if (axis) g_cy[(b * RSEL + r) * SPAN + k] = v;
        else      g_cx[(b * RSEL + r) * SPAN + k] = v;
    }
}

// ---------------------------------------------------------------------------
// K2: ROI pooling. Grid (RSEL, BATCH, NCGB=4) x 256. Warp = 8 channels
// interleaved (16 outstanding loads/lane); lanes = 16 x x 2 y-phases.
// ---------------------------------------------------------------------------
__global__ void roi_pool_kernel(const float* __restrict__ f0,
                                const float* __restrict__ f1,
                                const float* __restrict__ f2,
                                const float* __restrict__ f3,
                                float* __restrict__ out)
{
    const int r   = blockIdx.x;
    const int b   = blockIdx.y;
    const int cg  = blockIdx.z;      // 64-channel group
    const int tid = threadIdx.x;
    const int idx = b * RSEL + r;

    __shared__ float s_cx[SPAN], s_cy[SPAN];
    __shared__ int   s_meta[8];

    if (tid < SPAN)                       s_cx[tid]        = g_cx[idx * SPAN + tid];
    else if (tid < 2 * SPAN)              s_cy[tid - SPAN] = g_cy[idx * SPAN + tid - SPAN];
    else if (tid >= 128 && tid < 136)     s_meta[tid - 128] = g_meta[idx * 8 + tid - 128];
    __syncthreads();

    float* outp = out + (size_t)idx * CCH + cg * 64;
    if (!s_meta[4]) {                     // invalid -> zeros for our 64 channels
        if (tid < 64) outp[tid] = 0.0f;
        return;
    }

    const int xlo = s_meta[0], Lx = s_meta[1];
    const int ylo = s_meta[2], Ly = s_meta[3];
    const int lv  = s_meta[5];
    const int H   = 200 >> lv;
    const float* feat = (lv == 0) ? f0 : (lv == 1) ? f1 : (lv == 2) ? f2 : f3;
    const size_t hw = (size_t)H * (size_t)H;

    const int w    = tid >> 5;
    const int lane = tid & 31;
    const int xi   = lane & 15;
    const int yh   = lane >> 4;
    const int c0   = cg * 64 + w * 8;

    const float* bp = feat + ((size_t)b * CCH + c0) * hw
                    + (size_t)ylo * H + xlo;

    float a0 = 0.f, a1 = 0.f, a2 = 0.f, a3 = 0.f;
    float a4 = 0.f, a5 = 0.f, a6 = 0.f, a7 = 0.f;
    for (int xb = xi; xb < Lx; xb += 16) {
        float cxv = s_cx[xb];
        float s0 = 0.f, s1 = 0.f, s2 = 0.f, s3 = 0.f;
        float s4 = 0.f, s5 = 0.f, s6 = 0.f, s7 = 0.f;
        #pragma unroll 2
        for (int yy = yh; yy < Ly; yy += 2) {
            float cyv = s_cy[yy];
            const float* p = bp + (size_t)yy * H + xb;
            s0 += cyv * __ldg(p);
            s1 += cyv * __ldg(p + hw);
            s2 += cyv * __ldg(p + 2 * hw);
            s3 += cyv * __ldg(p + 3 * hw);
            s4 += cyv * __ldg(p + 4 * hw);
            s5 += cyv * __ldg(p + 5 * hw);
            s6 += cyv * __ldg(p + 6 * hw);
            s7 += cyv * __ldg(p + 7 * hw);
        }
        a0 += s0 * cxv; a1 += s1 * cxv; a2 += s2 * cxv; a3 += s3 * cxv;
        a4 += s4 * cxv; a5 += s5 * cxv; a6 += s6 * cxv; a7 += s7 * cxv;
    }

    #pragma unroll
    for (int o = 16; o; o >>= 1) {
        a0 += __shfl_xor_sync(0xffffffffu, a0, o);
        a1 += __shfl_xor_sync(0xffffffffu, a1, o);
        a2 += __shfl_xor_sync(0xffffffffu, a2, o);
        a3 += __shfl_xor_sync(0xffffffffu, a3, o);
        a4 += __shfl_xor_sync(0xffffffffu, a4, o);
        a5 += __shfl_xor_sync(0xffffffffu, a5, o);
        a6 += __shfl_xor_sync(0xffffffffu, a6, o);
        a7 += __shfl_xor_sync(0xffffffffu, a7, o);
    }
    if (lane == 0) {
        const float sc = 1.0f / 196.0f;
        float4 v0 = make_float4(a0 * sc, a1 * sc, a2 * sc, a3 * sc);
        float4 v1 = make_float4(a4 * sc, a5 * sc, a6 * sc, a7 * sc);
        *(float4*)(outp + w * 8)     = v0;
        *(float4*)(outp + w * 8 + 4) = v1;
    }
}

// ---------------------------------------------------------------------------
extern "C" void kernel_launch(void* const* d_in, const int* in_sizes, int n_in,
                              void* d_out, int out_size)
{
    const float* boxes  = (const float*)d_in[0];
    const float* scores = (const float*)d_in[1];
    const float* f0     = (const float*)d_in[2];
    const float* f1     = (const float*)d_in[3];
    const float* f2     = (const float*)d_in[4];
    const float* f3     = (const float*)d_in[5];
    float* out = (float*)d_out;

    nms_kernel<<<BATCH, 320>>>(boxes, scores);
    roi_pool_kernel<<<dim3(RSEL, BATCH, NCGB), 256>>>(f0, f1, f2, f3, out);
}

// round 8
// speedup vs baseline: 1.9501x; 1.9501x over previous
#include <cuda_runtime.h>
#include <math.h>

#define NB    300
#define BATCH 8
#define RSEL  36
#define NW    10
#define CCH   256
#define GRID  14
#define SPAN  64
#define NSEL  (BATCH * RSEL)
#define NCGB  16             // channel-group blocks (16 channels each)
#define CONF_THR 0.3f
#define IOU_THR  0.7f

// Inter-kernel scratch (device globals; no allocations allowed)
__device__ float4   g_sbox[BATCH * NB];       // sorted boxes
__device__ unsigned g_vinit[BATCH * NW];      // initial keep words (validity)
__device__ unsigned g_sup[BATCH * NB * NW];   // suppression masks
__device__ float    g_cx[NSEL * SPAN];        // separable x coefficients
__device__ float    g_cy[NSEL * SPAN];        // separable y coefficients
__device__ int      g_meta[NSEL * 8];         // xlo, Lx, ylo, Ly, valid, lv, 0, 0

// ---------------------------------------------------------------------------
// K1: per-batch threshold + stable rank sort + gather. 8 blocks x 320.
// ---------------------------------------------------------------------------
__global__ void k1_sort(const float* __restrict__ boxes,
                        const float* __restrict__ scores)
{
    const int b = blockIdx.x;
    const int t = threadIdx.x;

    __shared__ float s_raw[NB];
    __shared__ int   s_order[NB];
    __shared__ float s_ss[NB];

    for (int i = t; i < NB; i += blockDim.x) {
        float sc = scores[b * NB + i];
        s_raw[i] = (sc > CONF_THR) ? sc : -INFINITY;
    }
    __syncthreads();

    for (int i = t; i < NB; i += blockDim.x) {
        float si = s_raw[i];
        int rank = 0;
        for (int j = 0; j < NB; j++) {
            float sj = s_raw[j];
            if (sj > si || (sj == si && j < i)) rank++;
        }
        s_order[rank] = i;
    }
    __syncthreads();

    for (int r = t; r < NB; r += blockDim.x) {
        int i = s_order[r];
        g_sbox[b * NB + r] = ((const float4*)boxes)[(size_t)b * NB + i];
        s_ss[r] = s_raw[i];
    }
    __syncthreads();

    if (t < NW) {
        unsigned bits = 0;
        for (int k = 0; k < 32; k++) {
            int j = t * 32 + k;
            if (j < NB && s_ss[j] > -INFINITY) bits |= (1u << k);
        }
        g_vinit[b * NW + t] = bits;
    }
}

// ---------------------------------------------------------------------------
// K2: suppression masks, parallel across (word, batch). Grid (NW, BATCH) x 320.
// ---------------------------------------------------------------------------
__global__ void k2_mask()
{
    const int w = blockIdx.x;
    const int b = blockIdx.y;
    const int t = threadIdx.x;

    __shared__ float4 s_j[32];
    __shared__ float  s_ja[32];

    if (t < 32) {
        int j = w * 32 + t;
        float4 bb = (j < NB) ? g_sbox[b * NB + j] : make_float4(0, 0, 0, 0);
        s_j[t]  = bb;
        s_ja[t] = (bb.z - bb.x) * (bb.w - bb.y);
    }
    __syncthreads();

    const int i = t;
    if (i >= NB) return;

    unsigned bits = 0;
    if (w * 32 + 31 > i) {
        float4 a = g_sbox[b * NB + i];
        float area_a = (a.z - a.x) * (a.w - a.y);
        #pragma unroll 4
        for (int k = 0; k < 32; k++) {
            int j = w * 32 + k;
            if (j < NB && j > i) {
                float4 bb = s_j[k];
                float ltx = fmaxf(a.x, bb.x);
                float lty = fmaxf(a.y, bb.y);
                float rbx = fminf(a.z, bb.z);
                float rby = fminf(a.w, bb.w);
                float iw = fmaxf(rbx - ltx, 0.0f);
                float ih = fmaxf(rby - lty, 0.0f);
                float inter = iw * ih;
                float iou = inter / (area_a + s_ja[k] - inter + 1e-9f);
                if (iou > IOU_THR) bits |= (1u << k);
            }
        }
    }
    g_sup[(b * NB + i) * NW + w] = bits;
}

// ---------------------------------------------------------------------------
// K3: sequential suppression + stable selection + level + coefficient build.
// 8 blocks x 320.
// ---------------------------------------------------------------------------
__global__ void k3_final()
{
    const int b = blockIdx.x;
    const int t = threadIdx.x;

    __shared__ unsigned s_sup[NB][NW];
    __shared__ unsigned s_keepw[NW];
    __shared__ int      s_sel[RSEL];
    __shared__ float4   s_selbox[RSEL];
    __shared__ float    s_coef[RSEL][2][SPAN];

    for (int e = t; e < NB * NW; e += blockDim.x)
        ((unsigned*)s_sup)[e] = g_sup[b * NB * NW + e];
    if (t < NW) s_keepw[t] = g_vinit[b * NW + t];
    for (int e = t; e < RSEL * 2 * SPAN; e += blockDim.x)
        ((float*)s_coef)[e] = 0.0f;
    __syncthreads();

    if (t < 32) {
        unsigned keepw = (t < NW) ? s_keepw[t] : 0u;
        for (int i = 0; i < NB; i++) {
            unsigned wv = __shfl_sync(0xffffffffu, keepw, i >> 5);
            if ((wv >> (i & 31)) & 1u) {
                if (t < NW) keepw &= ~s_sup[i][t];
            }
        }
        if (t < NW) s_keepw[t] = keepw;
    }
    __syncthreads();

    if (t == 0) {
        int cnt = 0;
        for (int w = 0; w < NW && cnt < RSEL; w++) {
            unsigned bits = s_keepw[w];
            while (bits && cnt < RSEL) {
                int k = __ffs(bits) - 1; bits &= bits - 1;
                s_sel[cnt++] = w * 32 + k;
            }
        }
        for (int w = 0; w < NW && cnt < RSEL; w++) {
            unsigned bits = ~s_keepw[w];
            if (w == NW - 1) bits &= (1u << (NB - (NW - 1) * 32)) - 1;
            while (bits && cnt < RSEL) {
                int k = __ffs(bits) - 1; bits &= bits - 1;
                s_sel[cnt++] = w * 32 + k;
            }
        }
    }
    __syncthreads();

    if (t < RSEL) {
        int j = s_sel[t];
        float4 bb = g_sbox[b * NB + j];
        s_selbox[t] = bb;
        int valid = (s_keepw[j >> 5] >> (j & 31)) & 1u;
        float dx = bb.z - bb.x, dy = bb.w - bb.y;
        float sz = sqrtf(fmaxf(dx * dx + dy * dy, 1e-12f));
        float lvf = fminf(fmaxf(floorf(4.0f + log2f(sz / 224.0f * 4.0f)), 2.0f), 5.0f);
        int base = (b * RSEL + t) * 8;
        g_meta[base + 4] = valid;
        g_meta[base + 5] = (int)lvf - 2;
        g_meta[base + 6] = 0;
        g_meta[base + 7] = 0;
    }
    __syncthreads();

    // coefficient build: task t -> (box r = t>>1, axis = t&1)
    if (t < 2 * RSEL) {
        const int r = t >> 1, axis = t & 1;
        float4 bb = s_selbox[r];
        float dx = bb.z - bb.x, dy = bb.w - bb.y;
        float sz = sqrtf(fmaxf(dx * dx + dy * dy, 1e-12f));
        float lvf = fminf(fmaxf(floorf(4.0f + log2f(sz / 224.0f * 4.0f)), 2.0f), 5.0f);
        int lv = (int)lvf - 2;
        int H = 200 >> lv;
        float c1 = axis ? bb.y : bb.x;
        float c2 = axis ? bb.w : bb.z;
        float rs = fmaxf(c2 - c1, 1.0f);

        int lo = 1 << 30, hi = -(1 << 30);
        #pragma unroll
        for (int s = 0; s < GRID; s++) {
            float g = ((float)s + 0.5f) / (float)GRID;
            float P = c1 + rs * g;
            if (P < -1.0f || P > (float)H) continue;
            float p = fminf(fmaxf(P, 0.0f), (float)(H - 1));
            int p0 = (int)floorf(p);
            int p1 = min(p0 + 1, H - 1);
            lo = min(lo, p0); hi = max(hi, p1);
        }
        int L;
        if (lo > hi) { lo = 0; L = 0; }
        else {
            L = hi - lo + 1;
            #pragma unroll
            for (int s = 0; s < GRID; s++) {
                float g = ((float)s + 0.5f) / (float)GRID;
                float P = c1 + rs * g;
                if (P < -1.0f || P > (float)H) continue;
                float p = fminf(fmaxf(P, 0.0f), (float)(H - 1));
                int p0 = (int)floorf(p);
                int p1 = min(p0 + 1, H - 1);
                float lp = p - (float)p0;
                s_coef[r][axis][p0 - lo] += 1.0f - lp;
                s_coef[r][axis][p1 - lo] += lp;
            }
        }
        int base = (b * RSEL + r) * 8 + axis * 2;
        g_meta[base + 0] = lo;
        g_meta[base + 1] = L;
    }
    __syncthreads();

    for (int e = t; e < RSEL * 2 * SPAN; e += blockDim.x) {
        int r    = e / (2 * SPAN);
        int axis = (e >> 6) & 1;
        int k    = e & (SPAN - 1);
        float v  = s_coef[r][axis][k];
        if (axis) g_cy[(b * RSEL + r) * SPAN + k] = v;
        else      g_cx[(b * RSEL + r) * SPAN + k] = v;
    }
}

// ---------------------------------------------------------------------------
// K4: ROI pooling. Grid (RSEL, BATCH, NCGB=16) x 128. Warp = 4 channels
// interleaved; lanes = 16 x-positions x 2 y-phases. 4608 blocks.
// ---------------------------------------------------------------------------
__global__ void roi_pool_kernel(const float* __restrict__ f0,
                                const float* __restrict__ f1,
                                const float* __restrict__ f2,
                                const float* __restrict__ f3,
                                float* __restrict__ out)
{
    const int r   = blockIdx.x;
    const int b   = blockIdx.y;
    const int cg  = blockIdx.z;      // 16-channel group
    const int tid = threadIdx.x;     // 0..127
    const int idx = b * RSEL + r;

    __shared__ float s_cx[SPAN], s_cy[SPAN];
    __shared__ int   s_meta[8];

    // coalesced staging: 64 + 64 coefs by all 128 threads; meta by 8 lanes
    if (tid < SPAN)        s_cx[tid]        = g_cx[idx * SPAN + tid];
    else                   s_cy[tid - SPAN] = g_cy[idx * SPAN + tid - SPAN];
    if (tid >= 96 && tid < 104) s_meta[tid - 96] = g_meta[idx * 8 + tid - 96];
    __syncthreads();

    float* outp = out + (size_t)idx * CCH + cg * 16;
    if (!s_meta[4]) {
        if (tid < 16) outp[tid] = 0.0f;
        return;
    }

    const int xlo = s_meta[0], Lx = s_meta[1];
    const int ylo = s_meta[2], Ly = s_meta[3];
    const int lv  = s_meta[5];
    const int H   = 200 >> lv;
    const float* feat = (lv == 0) ? f0 : (lv == 1) ? f1 : (lv == 2) ? f2 : f3;
    const size_t hw = (size_t)H * (size_t)H;

    const int w    = tid >> 5;       // 0..3
    const int lane = tid & 31;
    const int xi   = lane & 15;
    const int yh   = lane >> 4;
    const int c0   = cg * 16 + w * 4;

    const float* bp = feat + ((size_t)b * CCH + c0) * hw
                    + (size_t)ylo * H + xlo;

    float a0 = 0.f, a1 = 0.f, a2 = 0.f, a3 = 0.f;
    for (int xb = xi; xb < Lx; xb += 16) {
        float cxv = s_cx[xb];
        float s0 = 0.f, s1 = 0.f, s2 = 0.f, s3 = 0.f;
        #pragma unroll 2
        for (int yy = yh; yy < Ly; yy += 2) {
            float cyv = s_cy[yy];
            const float* p = bp + (size_t)yy * H + xb;
            s0 += cyv * __ldg(p);
            s1 += cyv * __ldg(p + hw);
            s2 += cyv * __ldg(p + 2 * hw);
            s3 += cyv * __ldg(p + 3 * hw);
        }
        a0 += s0 * cxv; a1 += s1 * cxv; a2 += s2 * cxv; a3 += s3 * cxv;
    }

    #pragma unroll
    for (int o = 16; o; o >>= 1) {
        a0 += __shfl_xor_sync(0xffffffffu, a0, o);
        a1 += __shfl_xor_sync(0xffffffffu, a1, o);
        a2 += __shfl_xor_sync(0xffffffffu, a2, o);
        a3 += __shfl_xor_sync(0xffffffffu, a3, o);
    }
    if (lane == 0) {
        const float sc = 1.0f / 196.0f;
        float4 v = make_float4(a0 * sc, a1 * sc, a2 * sc, a3 * sc);
        *(float4*)(outp + w * 4) = v;
    }
}

// ---------------------------------------------------------------------------
extern "C" void kernel_launch(void* const* d_in, const int* in_sizes, int n_in,
                              void* d_out, int out_size)
{
    const float* boxes  = (const float*)d_in[0];
    const float* scores = (const float*)d_in[1];
    const float* f0     = (const float*)d_in[2];
    const float* f1     = (const float*)d_in[3];
    const float* f2     = (const float*)d_in[4];
    const float* f3     = (const float*)d_in[5];
    float* out = (float*)d_out;

    k1_sort<<<BATCH, 320>>>(boxes, scores);
    k2_mask<<<dim3(NW, BATCH), 320>>>();
    k3_final<<<BATCH, 320>>>();
    roi_pool_kernel<<<dim3(RSEL, BATCH, NCGB), 128>>>(f0, f1, f2, f3, out);
}

// round 9
// speedup vs baseline: 2.1073x; 1.0806x over previous
#include <cuda_runtime.h>
#include <math.h>

#define NB    300
#define BATCH 8
#define RSEL  36
#define NW    10
#define CCH   256
#define GRID  14
#define SPAN  64
#define NSEL  (BATCH * RSEL)
#define NCGB  32             // channel-group blocks (8 channels each)
#define CONF_THR 0.3f
#define IOU_THR  0.7f

// Inter-kernel scratch (device globals; no allocations allowed)
__device__ float4   g_sbox[BATCH * NB];       // sorted boxes
__device__ unsigned g_vinit[BATCH * NW];      // initial keep words (validity)
__device__ unsigned g_sup[BATCH * NB * NW];   // suppression masks
__device__ float    g_cx[NSEL * SPAN];        // separable x coefficients
__device__ float    g_cy[NSEL * SPAN];        // separable y coefficients
__device__ int      g_meta[NSEL * 8];         // xlo, Lx, ylo, Ly, valid, lv, 0, 0

// ---------------------------------------------------------------------------
// K12: threshold + stable sort (redundant per block) + suppression-mask word.
// Grid (NW, BATCH) x 320. Block w==0 also emits sorted boxes + validity words.
// ---------------------------------------------------------------------------
__global__ void k12_mask(const float* __restrict__ boxes,
                         const float* __restrict__ scores)
{
    const int w = blockIdx.x;
    const int b = blockIdx.y;
    const int t = threadIdx.x;

    __shared__ float  s_raw[NB];
    __shared__ int    s_order[NB];
    __shared__ float4 s_box[NB];
    __shared__ float  s_area[NB];
    __shared__ float  s_ss[NB];

    // threshold
    for (int i = t; i < NB; i += blockDim.x) {
        float sc = scores[b * NB + i];
        s_raw[i] = (sc > CONF_THR) ? sc : -INFINITY;
    }
    __syncthreads();

    // stable descending rank sort
    for (int i = t; i < NB; i += blockDim.x) {
        float si = s_raw[i];
        int rank = 0;
        for (int j = 0; j < NB; j++) {
            float sj = s_raw[j];
            if (sj > si || (sj == si && j < i)) rank++;
        }
        s_order[rank] = i;
    }
    __syncthreads();

    // gather sorted boxes / areas / scores
    for (int r = t; r < NB; r += blockDim.x) {
        int i = s_order[r];
        float4 bb = ((const float4*)boxes)[(size_t)b * NB + i];
        s_box[r]  = bb;
        s_area[r] = (bb.z - bb.x) * (bb.w - bb.y);
        s_ss[r]   = s_raw[i];
    }
    __syncthreads();

    // block w==0 publishes sorted boxes + validity words for k3
    if (w == 0) {
        for (int r = t; r < NB; r += blockDim.x)
            g_sbox[b * NB + r] = s_box[r];
        int pred = (t < NB) && (s_ss[t] > -INFINITY);
        unsigned word = __ballot_sync(0xffffffffu, pred);
        if ((t & 31) == 0) g_vinit[b * NW + (t >> 5)] = word;   // 320 thr = 10 words
    }

    // suppression word w of row i: bit k set iff j=w*32+k > i && iou > thr
    const int i = t;
    if (i >= NB) return;

    unsigned bits = 0;
    if (w * 32 + 31 > i) {
        float4 a = s_box[i];
        float area_a = s_area[i];
        #pragma unroll 4
        for (int k = 0; k < 32; k++) {
            int j = w * 32 + k;
            if (j < NB && j > i) {
                float4 bb = s_box[j];
                float ltx = fmaxf(a.x, bb.x);
                float lty = fmaxf(a.y, bb.y);
                float rbx = fminf(a.z, bb.z);
                float rby = fminf(a.w, bb.w);
                float iw = fmaxf(rbx - ltx, 0.0f);
                float ih = fmaxf(rby - lty, 0.0f);
                float inter = iw * ih;
                float iou = inter / (area_a + s_area[j] - inter + 1e-9f);
                if (iou > IOU_THR) bits |= (1u << k);
            }
        }
    }
    g_sup[(b * NB + i) * NW + w] = bits;
}

// ---------------------------------------------------------------------------
// K3: sequential suppression + stable selection + level + coefficient build.
// 8 blocks x 320.
// ---------------------------------------------------------------------------
__global__ void k3_final()
{
    const int b = blockIdx.x;
    const int t = threadIdx.x;

    __shared__ unsigned s_sup[NB][NW];
    __shared__ unsigned s_keepw[NW];
    __shared__ int      s_sel[RSEL];
    __shared__ float4   s_selbox[RSEL];
    __shared__ float    s_coef[RSEL][2][SPAN];

    for (int e = t; e < NB * NW; e += blockDim.x)
        ((unsigned*)s_sup)[e] = g_sup[b * NB * NW + e];
    if (t < NW) s_keepw[t] = g_vinit[b * NW + t];
    for (int e = t; e < RSEL * 2 * SPAN; e += blockDim.x)
        ((float*)s_coef)[e] = 0.0f;
    __syncthreads();

    if (t < 32) {
        unsigned keepw = (t < NW) ? s_keepw[t] : 0u;
        for (int i = 0; i < NB; i++) {
            unsigned wv = __shfl_sync(0xffffffffu, keepw, i >> 5);
            if ((wv >> (i & 31)) & 1u) {
                if (t < NW) keepw &= ~s_sup[i][t];
            }
        }
        if (t < NW) s_keepw[t] = keepw;
    }
    __syncthreads();

    if (t == 0) {
        int cnt = 0;
        for (int w = 0; w < NW && cnt < RSEL; w++) {
            unsigned bits = s_keepw[w];
            while (bits && cnt < RSEL) {
                int k = __ffs(bits) - 1; bits &= bits - 1;
                s_sel[cnt++] = w * 32 + k;
            }
        }
        for (int w = 0; w < NW && cnt < RSEL; w++) {
            unsigned bits = ~s_keepw[w];
            if (w == NW - 1) bits &= (1u << (NB - (NW - 1) * 32)) - 1;
            while (bits && cnt < RSEL) {
                int k = __ffs(bits) - 1; bits &= bits - 1;
                s_sel[cnt++] = w * 32 + k;
            }
        }
    }
    __syncthreads();

    if (t < RSEL) {
        int j = s_sel[t];
        float4 bb = g_sbox[b * NB + j];
        s_selbox[t] = bb;
        int valid = (s_keepw[j >> 5] >> (j & 31)) & 1u;
        float dx = bb.z - bb.x, dy = bb.w - bb.y;
        float sz = sqrtf(fmaxf(dx * dx + dy * dy, 1e-12f));
        float lvf = fminf(fmaxf(floorf(4.0f + log2f(sz / 224.0f * 4.0f)), 2.0f), 5.0f);
        int base = (b * RSEL + t) * 8;
        g_meta[base + 4] = valid;
        g_meta[base + 5] = (int)lvf - 2;
        g_meta[base + 6] = 0;
        g_meta[base + 7] = 0;
    }
    __syncthreads();

    // coefficient build: task t -> (box r = t>>1, axis = t&1)
    if (t < 2 * RSEL) {
        const int r = t >> 1, axis = t & 1;
        float4 bb = s_selbox[r];
        float dx = bb.z - bb.x, dy = bb.w - bb.y;
        float sz = sqrtf(fmaxf(dx * dx + dy * dy, 1e-12f));
        float lvf = fminf(fmaxf(floorf(4.0f + log2f(sz / 224.0f * 4.0f)), 2.0f), 5.0f);
        int lv = (int)lvf - 2;
        int H = 200 >> lv;
        float c1 = axis ? bb.y : bb.x;
        float c2 = axis ? bb.w : bb.z;
        float rs = fmaxf(c2 - c1, 1.0f);

        int lo = 1 << 30, hi = -(1 << 30);
        #pragma unroll
        for (int s = 0; s < GRID; s++) {
            float g = ((float)s + 0.5f) / (float)GRID;
            float P = c1 + rs * g;
            if (P < -1.0f || P > (float)H) continue;
            float p = fminf(fmaxf(P, 0.0f), (float)(H - 1));
            int p0 = (int)floorf(p);
            int p1 = min(p0 + 1, H - 1);
            lo = min(lo, p0); hi = max(hi, p1);
        }
        int L;
        if (lo > hi) { lo = 0; L = 0; }
        else {
            L = hi - lo + 1;
            #pragma unroll
            for (int s = 0; s < GRID; s++) {
                float g = ((float)s + 0.5f) / (float)GRID;
                float P = c1 + rs * g;
                if (P < -1.0f || P > (float)H) continue;
                float p = fminf(fmaxf(P, 0.0f), (float)(H - 1));
                int p0 = (int)floorf(p);
                int p1 = min(p0 + 1, H - 1);
                float lp = p - (float)p0;
                s_coef[r][axis][p0 - lo] += 1.0f - lp;
                s_coef[r][axis][p1 - lo] += lp;
            }
        }
        int base = (b * RSEL + r) * 8 + axis * 2;
        g_meta[base + 0] = lo;
        g_meta[base + 1] = L;
    }
    __syncthreads();

    for (int e = t; e < RSEL * 2 * SPAN; e += blockDim.x) {
        int r    = e / (2 * SPAN);
        int axis = (e >> 6) & 1;
        int k    = e & (SPAN - 1);
        float v  = s_coef[r][axis][k];
        if (axis) g_cy[(b * RSEL + r) * SPAN + k] = v;
        else      g_cx[(b * RSEL + r) * SPAN + k] = v;
    }
}

// ---------------------------------------------------------------------------
// K4: ROI pooling, stage-free. Grid (RSEL, BATCH, NCGB=32) x 64.
// Warp = 4 channels interleaved; lanes = 16 x-positions x 2 y-phases.
// Coefs/meta read via __ldg (L1-hot: 32 blocks share each ROI's 512B).
// ---------------------------------------------------------------------------
__global__ void roi_pool_kernel(const float* __restrict__ f0,
                                const float* __restrict__ f1,
                                const float* __restrict__ f2,
                                const float* __restrict__ f3,
                                float* __restrict__ out)
{
    const int r   = blockIdx.x;
    const int b   = blockIdx.y;
    const int cg  = blockIdx.z;      // 8-channel group
    const int tid = threadIdx.x;     // 0..63
    const int idx = b * RSEL + r;

    const int* mp = g_meta + idx * 8;
    float* outp = out + (size_t)idx * CCH + cg * 8;

    const int valid = __ldg(mp + 4);
    if (!valid) {
        if (tid < 8) outp[tid] = 0.0f;
        return;
    }

    const int xlo = __ldg(mp + 0);
    const int Lx  = __ldg(mp + 1);
    const int ylo = __ldg(mp + 2);
    const int Ly  = __ldg(mp + 3);
    const int lv  = __ldg(mp + 5);
    const int H   = 200 >> lv;
    const float* feat = (lv == 0) ? f0 : (lv == 1) ? f1 : (lv == 2) ? f2 : f3;
    const size_t hw = (size_t)H * (size_t)H;

    const float* cxp = g_cx + idx * SPAN;
    const float* cyp = g_cy + idx * SPAN;

    const int w    = tid >> 5;       // 0..1
    const int lane = tid & 31;
    const int xi   = lane & 15;
    const int yh   = lane >> 4;
    const int c0   = cg * 8 + w * 4;

    const float* bp = feat + ((size_t)b * CCH + c0) * hw
                    + (size_t)ylo * H + xlo;

    float a0 = 0.f, a1 = 0.f, a2 = 0.f, a3 = 0.f;
    for (int xb = xi; xb < Lx; xb += 16) {
        float cxv = __ldg(cxp + xb);
        float s0 = 0.f, s1 = 0.f, s2 = 0.f, s3 = 0.f;
        #pragma unroll 2
        for (int yy = yh; yy < Ly; yy += 2) {
            float cyv = __ldg(cyp + yy);
            const float* p = bp + (size_t)yy * H + xb;
            s0 += cyv * __ldg(p);
            s1 += cyv * __ldg(p + hw);
            s2 += cyv * __ldg(p + 2 * hw);
            s3 += cyv * __ldg(p + 3 * hw);
        }
        a0 += s0 * cxv; a1 += s1 * cxv; a2 += s2 * cxv; a3 += s3 * cxv;
    }

    #pragma unroll
    for (int o = 16; o; o >>= 1) {
        a0 += __shfl_xor_sync(0xffffffffu, a0, o);
        a1 += __shfl_xor_sync(0xffffffffu, a1, o);
        a2 += __shfl_xor_sync(0xffffffffu, a2, o);
        a3 += __shfl_xor_sync(0xffffffffu, a3, o);
    }
    if (lane == 0) {
        const float sc = 1.0f / 196.0f;
        float4 v = make_float4(a0 * sc, a1 * sc, a2 * sc, a3 * sc);
        *(float4*)(outp + w * 4) = v;
    }
}

// ---------------------------------------------------------------------------
extern "C" void kernel_launch(void* const* d_in, const int* in_sizes, int n_in,
                              void* d_out, int out_size)
{
    const float* boxes  = (const float*)d_in[0];
    const float* scores = (const float*)d_in[1];
    const float* f0     = (const float*)d_in[2];
    const float* f1     = (const float*)d_in[3];
    const float* f2     = (const float*)d_in[4];
    const float* f3     = (const float*)d_in[5];
    float* out = (float*)d_out;

    k12_mask<<<dim3(NW, BATCH), 320>>>(boxes, scores);
    k3_final<<<BATCH, 320>>>();
    roi_pool_kernel<<<dim3(RSEL, BATCH, NCGB), 64>>>(f0, f1, f2, f3, out);
}